// round 7
// baseline (speedup 1.0000x reference)
#include <cuda_runtime.h>
#include <math.h>

#define NE     8
#define DDIM   512
#define HDIM   2048
#define NTOK   1024
#define NSLOT  2048   // NTOK * top_k

// ---------------- scratch (device globals; no allocation allowed) -----------
// NOTE: these are referenced ONLY from device code. Passing a __device__
// symbol as a kernel argument from host code yields the HOST shadow address,
// and on GB300 (ATS/HMM) the GPU silently writes host DRAM instead of
// faulting — that was the R1-R6 bug.
__device__ __align__(16) float g_hidden[(size_t)NSLOT * HDIM];  // 16 MB
__device__ __align__(16) float g_z[(size_t)NSLOT * DDIM];       // 4 MB
__device__ int   g_rows[NE * NSLOT];
__device__ int   g_cnt[NE];
__device__ float g_score[NSLOT];

__device__ __forceinline__ bool is_zero8(const float* p) {
    float s = 0.f;
#pragma unroll
    for (int i = 0; i < 8; i++) s += fabsf(p[i]);
    return s == 0.f;
}

// ---------------- init -------------------------------------------------------
__global__ void zero_cnt_kernel() {
    if (threadIdx.x < NE) g_cnt[threadIdx.x] = 0;
}

// ---------------- gate: logits -> top2 -> softmax -> bin --------------------
__global__ void gate_kernel(const float* __restrict__ inp,
                            const float* __restrict__ c0,
                            const float* __restrict__ c1,
                            const float* __restrict__ gb) {
    const float* gw = is_zero8(c0) ? c1 : c0;

    int warp = threadIdx.x >> 5;
    int lane = threadIdx.x & 31;
    int n = blockIdx.x * (blockDim.x >> 5) + warp;
    if (n >= NTOK) return;

    float acc[NE];
#pragma unroll
    for (int e = 0; e < NE; e++) acc[e] = 0.f;

    const float* x = inp + (size_t)n * DDIM;
    for (int d = lane; d < DDIM; d += 32) {
        float xv = x[d];
#pragma unroll
        for (int e = 0; e < NE; e++) acc[e] += xv * gw[e * DDIM + d];
    }
#pragma unroll
    for (int e = 0; e < NE; e++) {
#pragma unroll
        for (int off = 16; off; off >>= 1)
            acc[e] += __shfl_xor_sync(0xFFFFFFFFu, acc[e], off);
    }
    if (lane == 0) {
        float v0 = -1e30f, v1 = -1e30f;
        int i0 = 0, i1 = 0;
#pragma unroll
        for (int e = 0; e < NE; e++) {
            float v = acc[e] + gb[e];
            if (v > v0) { v1 = v0; i1 = i0; v0 = v; i0 = e; }
            else if (v > v1) { v1 = v; i1 = e; }
        }
        float ex = expf(v1 - v0);
        float s0 = 1.f / (1.f + ex);
        float s1 = ex * s0;
        g_score[2 * n + 0] = s0;
        g_score[2 * n + 1] = s1;
        int p0 = atomicAdd(&g_cnt[i0], 1);
        g_rows[i0 * NSLOT + p0] = 2 * n;
        int p1 = atomicAdd(&g_cnt[i1], 1);
        g_rows[i1 * NSLOT + p1] = 2 * n + 1;
    }
}

// ---------------- pad row lists to full length with -1 ----------------------
__global__ void pad_rows_kernel() {
    int e = blockIdx.x;
    int cnt = g_cnt[e];
    for (int i = cnt + threadIdx.x; i < NSLOT; i += blockDim.x)
        g_rows[e * NSLOT + i] = -1;
}

// ---------------- grouped GEMM: C[slot] = A_row @ W[e]^T + bias -------------
// FC1 (FC2F=false): A = inp (param, slot>>1 row), C = g_hidden (symbol), GeLU.
// FC2 (FC2F=true):  A = g_hidden (symbol),        C = g_z (symbol).
template <int TM, int TN, int KK, int NOUT, bool GELU, bool PICK_ZERO_BIAS, bool FC2F>
__global__ void __launch_bounds__((TM/8)*(TN/8), 1)
moe_gemm_kernel(const float* __restrict__ Ain,    // used only for FC1 (= inp)
                const float* __restrict__ W,      // E x NOUT x KK
                const float* __restrict__ bias0,  // E x NOUT
                const float* __restrict__ bias1) {
    constexpr int TK = 8;
    constexpr int TX = TN / 8;
    constexpr int TY = TM / 8;
    constexpr int NT = TX * TY;

    const float* A   = FC2F ? g_hidden : Ain;
    float*       Cout = FC2F ? g_z : g_hidden;
    const int    lda = FC2F ? HDIM : DDIM;

    const float* bias = bias0;
    if (PICK_ZERO_BIAS) bias = is_zero8(bias0) ? bias0 : bias1;

    const int e  = blockIdx.z;
    const int rt = blockIdx.y;
    const int ct = blockIdx.x;

    __shared__ float As[TK][TM];
    __shared__ float Bs[TK][TN];
    __shared__ int   sslot[TM];

    const int t = threadIdx.x;
    const int tx = t % TX;
    const int ty = t / TX;

    const int* rows = g_rows + e * NSLOT + rt * TM;
    for (int i = t; i < TM; i += NT) sslot[i] = rows[i];
    __syncthreads();
    if (sslot[0] < 0) return;   // packed list => whole tile empty; uniform exit

    float acc[8][8];
#pragma unroll
    for (int ii = 0; ii < 8; ii++)
#pragma unroll
        for (int jj = 0; jj < 8; jj++) acc[ii][jj] = 0.f;

    const float* Wb = W + (size_t)e * NOUT * KK + (size_t)(ct * TN) * KK;

    for (int k0 = 0; k0 < KK; k0 += TK) {
        constexpr int AF4 = TK * TM / 4;
        for (int f = t; f < AF4; f += NT) {
            int i  = f / (TK / 4);
            int kq = f % (TK / 4);
            int slot = sslot[i];
            float4 v = make_float4(0.f, 0.f, 0.f, 0.f);
            if (slot >= 0) {
                int arow = FC2F ? slot : (slot >> 1);
                v = *(const float4*)(A + (size_t)arow * lda + k0 + kq * 4);
            }
            As[kq * 4 + 0][i] = v.x;
            As[kq * 4 + 1][i] = v.y;
            As[kq * 4 + 2][i] = v.z;
            As[kq * 4 + 3][i] = v.w;
        }
        constexpr int BF4 = TK * TN / 4;
        for (int f = t; f < BF4; f += NT) {
            int j  = f / (TK / 4);
            int kq = f % (TK / 4);
            float4 v = *(const float4*)(Wb + (size_t)j * KK + k0 + kq * 4);
            Bs[kq * 4 + 0][j] = v.x;
            Bs[kq * 4 + 1][j] = v.y;
            Bs[kq * 4 + 2][j] = v.z;
            Bs[kq * 4 + 3][j] = v.w;
        }
        __syncthreads();

#pragma unroll
        for (int kk = 0; kk < TK; kk++) {
            float a[8], b[8];
#pragma unroll
            for (int q = 0; q < 4; q++) {
                a[q]     = As[kk][ty * 4 + q];
                a[q + 4] = As[kk][TM / 2 + ty * 4 + q];
                b[q]     = Bs[kk][tx * 4 + q];
                b[q + 4] = Bs[kk][TN / 2 + tx * 4 + q];
            }
#pragma unroll
            for (int ii = 0; ii < 8; ii++)
#pragma unroll
                for (int jj = 0; jj < 8; jj++)
                    acc[ii][jj] = fmaf(a[ii], b[jj], acc[ii][jj]);
        }
        __syncthreads();
    }

    const int colbase = ct * TN;
#pragma unroll
    for (int ii = 0; ii < 8; ii++) {
        int i = (ii < 4) ? (ty * 4 + ii) : (TM / 2 + ty * 4 + (ii - 4));
        int slot = sslot[i];
        if (slot < 0) continue;
#pragma unroll
        for (int jj = 0; jj < 8; jj++) {
            int j = (jj < 4) ? (tx * 4 + jj) : (TN / 2 + tx * 4 + (jj - 4));
            float v = acc[ii][jj] + bias[e * NOUT + colbase + j];
            if (GELU) v = 0.5f * v * (1.f + erff(v * 0.70710678118654752f));
            Cout[(size_t)slot * NOUT + colbase + j] = v;
        }
    }
}

// ---------------- combine (top-2 weighted sum) + LayerNorm ------------------
__global__ void combine_ln_kernel(const float* __restrict__ l0,
                                  const float* __restrict__ l1,
                                  float* __restrict__ out) {
    const float* ln_b = is_zero8(l0) ? l0 : l1;
    const float* ln_w = is_zero8(l0) ? l1 : l0;

    const int n = blockIdx.x;
    const int t = threadIdx.x;  // 256 threads
    __shared__ float buf[DDIM];
    __shared__ float wsum[8], wsq[8];

    float s0 = g_score[2 * n + 0];
    float s1 = g_score[2 * n + 1];
    const float* z0 = g_z + (size_t)(2 * n + 0) * DDIM;
    const float* z1 = g_z + (size_t)(2 * n + 1) * DDIM;

    float sum = 0.f, sq = 0.f;
    for (int d = t; d < DDIM; d += 256) {
        float v = s0 * z0[d] + s1 * z1[d];
        buf[d] = v;
        sum += v;
        sq += v * v;
    }
#pragma unroll
    for (int off = 16; off; off >>= 1) {
        sum += __shfl_xor_sync(0xFFFFFFFFu, sum, off);
        sq  += __shfl_xor_sync(0xFFFFFFFFu, sq, off);
    }
    int warp = t >> 5, lane = t & 31;
    if (lane == 0) { wsum[warp] = sum; wsq[warp] = sq; }
    __syncthreads();
    if (warp == 0) {
        float s = (lane < 8) ? wsum[lane] : 0.f;
        float q = (lane < 8) ? wsq[lane] : 0.f;
#pragma unroll
        for (int off = 4; off; off >>= 1) {
            s += __shfl_xor_sync(0xFFFFFFFFu, s, off);
            q += __shfl_xor_sync(0xFFFFFFFFu, q, off);
        }
        if (lane == 0) { wsum[0] = s; wsq[0] = q; }
    }
    __syncthreads();
    float mean = wsum[0] * (1.f / DDIM);
    float var  = wsq[0] * (1.f / DDIM) - mean * mean;
    float inv  = rsqrtf(var + 1e-5f);
    for (int d = t; d < DDIM; d += 256) {
        out[(size_t)n * DDIM + d] = (buf[d] - mean) * inv * ln_w[d] + ln_b[d];
    }
}

// ---------------- slim diagnostic (writes only on invariant failure) --------
//  C=2: gate broken | C=5: g_hidden still zero | C=9: g_z still zero
__global__ void diag_kernel(float* out) {
    __shared__ float sC;
    if (threadIdx.x == 0) {
        float C = 0.f;
        int s = 0;
        for (int e = 0; e < NE; e++) s += g_cnt[e];
        if (s != NSLOT) C = 2.f;
        else {
            bool hz = true;
            for (int i = 0; i < 256 && hz; i++)
                if (g_hidden[(size_t)i * 8192] != 0.f) hz = false;
            if (hz) C = 5.f;
            else {
                bool zz = true;
                for (int i = 0; i < 256 && zz; i++)
                    if (g_z[(size_t)i * 4093] != 0.f) zz = false;
                if (zz) C = 9.f;
            }
        }
        sC = C;
    }
    __syncthreads();
    float C = sC;
    if (C != 0.f) {
        for (size_t i = threadIdx.x; i < (size_t)NTOK * DDIM; i += blockDim.x)
            out[i] = C;
    }
}

// ---------------- launch -----------------------------------------------------
extern "C" void kernel_launch(void* const* d_in, const int* in_sizes, int n_in,
                              void* d_out, int out_size) {
    (void)out_size;
    const float *inp = nullptr, *gb = nullptr, *b1 = nullptr;
    const float *w1 = nullptr, *w2 = nullptr;
    const float *p4096[2] = {nullptr, nullptr};
    const float *p512[2]  = {nullptr, nullptr};
    int n4096 = 0, n512 = 0;

    for (int i = 0; i < n_in; i++) {
        const float* p = (const float*)d_in[i];
        switch (in_sizes[i]) {
            case NTOK * DDIM:      inp = p; break;
            case NE:               gb = p; break;
            case NE * HDIM:        b1 = p; break;
            case NE * HDIM * DDIM: if (!w1) w1 = p; else w2 = p; break;
            case NE * DDIM:        if (n4096 < 2) p4096[n4096++] = p; break;
            case DDIM:             if (n512 < 2) p512[n512++] = p; break;
            default: break;
        }
    }
    if (n_in >= 9) {
        if (!inp)  inp = (const float*)d_in[0];
        if (n4096 < 1) p4096[n4096++] = (const float*)d_in[1];
        if (!gb)   gb  = (const float*)d_in[2];
        if (!w1)   w1  = (const float*)d_in[3];
        if (!b1)   b1  = (const float*)d_in[4];
        if (!w2)   w2  = (const float*)d_in[5];
        if (n4096 < 2) p4096[n4096++] = (const float*)d_in[6];
        if (n512 < 1)  p512[n512++]   = (const float*)d_in[7];
        if (n512 < 2)  p512[n512++]   = (const float*)d_in[8];
    }
    if (n4096 == 1) p4096[1] = p4096[0];
    if (n512 == 1)  p512[1]  = p512[0];
    float* out = (float*)d_out;

    zero_cnt_kernel<<<1, 32>>>();
    gate_kernel<<<NTOK / 8, 256>>>(inp, p4096[0], p4096[1], gb);
    pad_rows_kernel<<<NE, 256>>>();

    // FC1 + GeLU: (NSLOT x DDIM) @ (HDIM x DDIM)^T per expert -> g_hidden
    moe_gemm_kernel<128, 128, DDIM, HDIM, true, false, false>
        <<<dim3(HDIM / 128, NSLOT / 128, NE), 256>>>(inp, w1, b1, b1);

    // FC2: (NSLOT x HDIM) @ (DDIM x HDIM)^T per expert -> g_z
    moe_gemm_kernel<128, 64, HDIM, DDIM, false, true, true>
        <<<dim3(DDIM / 64, NSLOT / 128, NE), 128>>>(nullptr, w2, p4096[0], p4096[1]);

    combine_ln_kernel<<<NTOK, 256>>>(p512[0], p512[1], out);

    diag_kernel<<<1, 256>>>(out);
}

// round 11
// speedup vs baseline: 1.6064x; 1.6064x over previous
#include <cuda_runtime.h>
#include <math.h>

#define NE     8
#define DDIM   512
#define HDIM   2048
#define NTOK   1024
#define NSLOT  2048   // NTOK * top_k

// ---------------- scratch (device globals; no allocation allowed) -----------
// Referenced ONLY from device code: passing a __device__ symbol as a kernel
// argument from host code yields the host shadow address (silent ATS write on
// GB300) — the R1-R6 bug.
__device__ __align__(16) float g_hidden[(size_t)NSLOT * HDIM];  // 16 MB
__device__ __align__(16) float g_z[(size_t)NSLOT * DDIM];       // 4 MB
__device__ int   g_rows[NE * NSLOT];
__device__ int   g_cnt[NE];
__device__ float g_score[NSLOT];

__device__ __forceinline__ bool is_zero8(const float* p) {
    float s = 0.f;
#pragma unroll
    for (int i = 0; i < 8; i++) s += fabsf(p[i]);
    return s == 0.f;
}

__device__ __forceinline__ unsigned f2tf32(float v) {
    unsigned u;
    asm("cvt.rna.tf32.f32 %0, %1;" : "=r"(u) : "f"(v));
    return u;
}

__device__ __forceinline__ void mma_tf32(float c[4], unsigned a0, unsigned a1,
                                         unsigned a2, unsigned a3,
                                         unsigned b0, unsigned b1) {
    asm volatile(
        "mma.sync.aligned.m16n8k8.row.col.f32.tf32.tf32.f32 "
        "{%0,%1,%2,%3}, {%4,%5,%6,%7}, {%8,%9}, {%0,%1,%2,%3};"
        : "+f"(c[0]), "+f"(c[1]), "+f"(c[2]), "+f"(c[3])
        : "r"(a0), "r"(a1), "r"(a2), "r"(a3), "r"(b0), "r"(b1));
}

// ---------------- init -------------------------------------------------------
__global__ void zero_cnt_kernel() {
    if (threadIdx.x < NE) g_cnt[threadIdx.x] = 0;
}

// ---------------- gate: logits -> top2 -> softmax -> bin --------------------
__global__ void gate_kernel(const float* __restrict__ inp,
                            const float* __restrict__ c0,
                            const float* __restrict__ c1,
                            const float* __restrict__ gb) {
    const float* gw = is_zero8(c0) ? c1 : c0;

    int warp = threadIdx.x >> 5;
    int lane = threadIdx.x & 31;
    int n = blockIdx.x * (blockDim.x >> 5) + warp;
    if (n >= NTOK) return;

    float acc[NE];
#pragma unroll
    for (int e = 0; e < NE; e++) acc[e] = 0.f;

    const float* x = inp + (size_t)n * DDIM;
    for (int d = lane; d < DDIM; d += 32) {
        float xv = x[d];
#pragma unroll
        for (int e = 0; e < NE; e++) acc[e] += xv * gw[e * DDIM + d];
    }
#pragma unroll
    for (int e = 0; e < NE; e++) {
#pragma unroll
        for (int off = 16; off; off >>= 1)
            acc[e] += __shfl_xor_sync(0xFFFFFFFFu, acc[e], off);
    }
    if (lane == 0) {
        float v0 = -1e30f, v1 = -1e30f;
        int i0 = 0, i1 = 0;
#pragma unroll
        for (int e = 0; e < NE; e++) {
            float v = acc[e] + gb[e];
            if (v > v0) { v1 = v0; i1 = i0; v0 = v; i0 = e; }
            else if (v > v1) { v1 = v; i1 = e; }
        }
        float ex = expf(v1 - v0);
        float s0 = 1.f / (1.f + ex);
        float s1 = ex * s0;
        g_score[2 * n + 0] = s0;
        g_score[2 * n + 1] = s1;
        int p0 = atomicAdd(&g_cnt[i0], 1);
        g_rows[i0 * NSLOT + p0] = 2 * n;
        int p1 = atomicAdd(&g_cnt[i1], 1);
        g_rows[i1 * NSLOT + p1] = 2 * n + 1;
    }
}

// ---------------- pad row lists to full length with -1 ----------------------
__global__ void pad_rows_kernel() {
    int e = blockIdx.x;
    int cnt = g_cnt[e];
    for (int i = cnt + threadIdx.x; i < NSLOT; i += blockDim.x)
        g_rows[e * NSLOT + i] = -1;
}

// ---------------- grouped GEMM via mma.sync tf32 -----------------------------
// C[slot] = A_row @ W[e]^T + bias. 256 threads = 8 warps (4 x 2 layout).
// Warp tile 32 x (TN/2). Smem: As[m][k], Bs[n][k], row stride KT+4 = 36
// (conflict-free fragment LDS: bank = 4*g + k).
template <int TM, int TN, int KK, int NOUT, bool GELU, bool PICK_ZERO_BIAS, bool FC2F>
__global__ void __launch_bounds__(256, 1)
moe_gemm_tc(const float* __restrict__ Ain,    // FC1: inp; FC2: unused
            const float* __restrict__ W,      // E x NOUT x KK
            const float* __restrict__ bias0,  // E x NOUT
            const float* __restrict__ bias1) {
    constexpr int KT = 32;
    constexpr int SA = KT + 4;        // 36 floats
    constexpr int WX = 2;
    constexpr int WN = TN / WX;       // FC1: 64, FC2: 32
    constexpr int MI = 2;             // 32 rows / 16
    constexpr int NI = WN / 8;        // FC1: 8, FC2: 4

    const float* A    = FC2F ? g_hidden : Ain;
    float*       Cout = FC2F ? g_z : g_hidden;
    const int    lda  = FC2F ? HDIM : DDIM;

    const float* bias = bias0;
    if (PICK_ZERO_BIAS) bias = is_zero8(bias0) ? bias0 : bias1;

    const int e  = blockIdx.z;
    const int rt = blockIdx.y;
    const int ct = blockIdx.x;

    __shared__ float As[TM * SA];
    __shared__ float Bs[TN * SA];
    __shared__ int   sslot[TM];

    const int t    = threadIdx.x;
    const int wid  = t >> 5;
    const int lane = t & 31;
    const int wy   = wid >> 1;        // 0..3
    const int wx   = wid & 1;         // 0..1
    const int g    = lane >> 2;       // 0..7
    const int tk   = lane & 3;        // 0..3

    const int* rows = g_rows + e * NSLOT + rt * TM;
    for (int i = t; i < TM; i += 256) sslot[i] = rows[i];
    __syncthreads();
    if (sslot[0] < 0) return;         // packed list => whole tile empty

    float acc[MI][NI][4];
#pragma unroll
    for (int mi = 0; mi < MI; mi++)
#pragma unroll
        for (int ni = 0; ni < NI; ni++)
#pragma unroll
            for (int q = 0; q < 4; q++) acc[mi][ni][q] = 0.f;

    const float* Wb = W + (size_t)e * NOUT * KK + (size_t)(ct * TN) * KK;

    for (int k0 = 0; k0 < KK; k0 += KT) {
        // stage A tile: TM x KT (float4 along k; no transpose)
        constexpr int AF4 = TM * (KT / 4);
#pragma unroll
        for (int f = t; f < AF4; f += 256) {
            int i  = f >> 3;          // row (KT/4 == 8)
            int kq = f & 7;
            int slot = sslot[i];
            float4 v = make_float4(0.f, 0.f, 0.f, 0.f);
            if (slot >= 0) {
                int arow = FC2F ? slot : (slot >> 1);
                v = *(const float4*)(A + (size_t)arow * lda + k0 + kq * 4);
            }
            float4 c;
            c.x = __uint_as_float(f2tf32(v.x));
            c.y = __uint_as_float(f2tf32(v.y));
            c.z = __uint_as_float(f2tf32(v.z));
            c.w = __uint_as_float(f2tf32(v.w));
            *(float4*)&As[i * SA + kq * 4] = c;
        }
        // stage B tile: TN x KT
        constexpr int BF4 = TN * (KT / 4);
#pragma unroll
        for (int f = t; f < BF4; f += 256) {
            int j  = f >> 3;
            int kq = f & 7;
            float4 v = *(const float4*)(Wb + (size_t)j * KK + k0 + kq * 4);
            float4 c;
            c.x = __uint_as_float(f2tf32(v.x));
            c.y = __uint_as_float(f2tf32(v.y));
            c.z = __uint_as_float(f2tf32(v.z));
            c.w = __uint_as_float(f2tf32(v.w));
            *(float4*)&Bs[j * SA + kq * 4] = c;
        }
        __syncthreads();

#pragma unroll
        for (int kc = 0; kc < KT; kc += 8) {
            unsigned af[MI][4];
#pragma unroll
            for (int mi = 0; mi < MI; mi++) {
                int m = wy * 32 + mi * 16;
                af[mi][0] = __float_as_uint(As[(m + g) * SA + kc + tk]);
                af[mi][1] = __float_as_uint(As[(m + g + 8) * SA + kc + tk]);
                af[mi][2] = __float_as_uint(As[(m + g) * SA + kc + tk + 4]);
                af[mi][3] = __float_as_uint(As[(m + g + 8) * SA + kc + tk + 4]);
            }
#pragma unroll
            for (int ni = 0; ni < NI; ni++) {
                int n = wx * WN + ni * 8;
                unsigned b0 = __float_as_uint(Bs[(n + g) * SA + kc + tk]);
                unsigned b1 = __float_as_uint(Bs[(n + g) * SA + kc + tk + 4]);
#pragma unroll
                for (int mi = 0; mi < MI; mi++)
                    mma_tf32(acc[mi][ni], af[mi][0], af[mi][1], af[mi][2], af[mi][3], b0, b1);
            }
        }
        __syncthreads();
    }

    // epilogue: bias (+gelu), scatter to Cout rows by slot
    const int colbase = ct * TN + wx * WN;
#pragma unroll
    for (int mi = 0; mi < MI; mi++) {
        int lr0 = wy * 32 + mi * 16 + g;
        int slot0 = sslot[lr0];
        int slot1 = sslot[lr0 + 8];
#pragma unroll
        for (int ni = 0; ni < NI; ni++) {
            int col = colbase + ni * 8 + 2 * tk;
            float b0 = bias[e * NOUT + col];
            float b1 = bias[e * NOUT + col + 1];
            if (slot0 >= 0) {
                float v0 = acc[mi][ni][0] + b0;
                float v1 = acc[mi][ni][1] + b1;
                if (GELU) {
                    v0 = 0.5f * v0 * (1.f + erff(v0 * 0.70710678118654752f));
                    v1 = 0.5f * v1 * (1.f + erff(v1 * 0.70710678118654752f));
                }
                Cout[(size_t)slot0 * NOUT + col]     = v0;
                Cout[(size_t)slot0 * NOUT + col + 1] = v1;
            }
            if (slot1 >= 0) {
                float v2 = acc[mi][ni][2] + b0;
                float v3 = acc[mi][ni][3] + b1;
                if (GELU) {
                    v2 = 0.5f * v2 * (1.f + erff(v2 * 0.70710678118654752f));
                    v3 = 0.5f * v3 * (1.f + erff(v3 * 0.70710678118654752f));
                }
                Cout[(size_t)slot1 * NOUT + col]     = v2;
                Cout[(size_t)slot1 * NOUT + col + 1] = v3;
            }
        }
    }
}

// ---------------- combine (top-2 weighted sum) + LayerNorm ------------------
__global__ void combine_ln_kernel(const float* __restrict__ l0,
                                  const float* __restrict__ l1,
                                  float* __restrict__ out) {
    const float* ln_b = is_zero8(l0) ? l0 : l1;
    const float* ln_w = is_zero8(l0) ? l1 : l0;

    const int n = blockIdx.x;
    const int t = threadIdx.x;  // 256 threads
    __shared__ float buf[DDIM];
    __shared__ float wsum[8], wsq[8];

    float s0 = g_score[2 * n + 0];
    float s1 = g_score[2 * n + 1];
    const float* z0 = g_z + (size_t)(2 * n + 0) * DDIM;
    const float* z1 = g_z + (size_t)(2 * n + 1) * DDIM;

    float sum = 0.f, sq = 0.f;
    for (int d = t; d < DDIM; d += 256) {
        float v = s0 * z0[d] + s1 * z1[d];
        buf[d] = v;
        sum += v;
        sq += v * v;
    }
#pragma unroll
    for (int off = 16; off; off >>= 1) {
        sum += __shfl_xor_sync(0xFFFFFFFFu, sum, off);
        sq  += __shfl_xor_sync(0xFFFFFFFFu, sq, off);
    }
    int warp = t >> 5, lane = t & 31;
    if (lane == 0) { wsum[warp] = sum; wsq[warp] = sq; }
    __syncthreads();
    if (warp == 0) {
        float s = (lane < 8) ? wsum[lane] : 0.f;
        float q = (lane < 8) ? wsq[lane] : 0.f;
#pragma unroll
        for (int off = 4; off; off >>= 1) {
            s += __shfl_xor_sync(0xFFFFFFFFu, s, off);
            q += __shfl_xor_sync(0xFFFFFFFFu, q, off);
        }
        if (lane == 0) { wsum[0] = s; wsq[0] = q; }
    }
    __syncthreads();
    float mean = wsum[0] * (1.f / DDIM);
    float var  = wsq[0] * (1.f / DDIM) - mean * mean;
    float inv  = rsqrtf(var + 1e-5f);
    for (int d = t; d < DDIM; d += 256) {
        out[(size_t)n * DDIM + d] = (buf[d] - mean) * inv * ln_w[d] + ln_b[d];
    }
}

// ---------------- slim diagnostic (writes only on invariant failure) --------
__global__ void diag_kernel(float* out) {
    __shared__ float sC;
    if (threadIdx.x == 0) {
        float C = 0.f;
        int s = 0;
        for (int e = 0; e < NE; e++) s += g_cnt[e];
        if (s != NSLOT) C = 2.f;
        else {
            bool hz = true;
            for (int i = 0; i < 256 && hz; i++)
                if (g_hidden[(size_t)i * 8192] != 0.f) hz = false;
            if (hz) C = 5.f;
            else {
                bool zz = true;
                for (int i = 0; i < 256 && zz; i++)
                    if (g_z[(size_t)i * 4093] != 0.f) zz = false;
                if (zz) C = 9.f;
            }
        }
        sC = C;
    }
    __syncthreads();
    float C = sC;
    if (C != 0.f) {
        for (size_t i = threadIdx.x; i < (size_t)NTOK * DDIM; i += blockDim.x)
            out[i] = C;
    }
}

// ---------------- launch -----------------------------------------------------
extern "C" void kernel_launch(void* const* d_in, const int* in_sizes, int n_in,
                              void* d_out, int out_size) {
    (void)out_size;
    const float *inp = nullptr, *gb = nullptr, *b1 = nullptr;
    const float *w1 = nullptr, *w2 = nullptr;
    const float *p4096[2] = {nullptr, nullptr};
    const float *p512[2]  = {nullptr, nullptr};
    int n4096 = 0, n512 = 0;

    for (int i = 0; i < n_in; i++) {
        const float* p = (const float*)d_in[i];
        switch (in_sizes[i]) {
            case NTOK * DDIM:      inp = p; break;
            case NE:               gb = p; break;
            case NE * HDIM:        b1 = p; break;
            case NE * HDIM * DDIM: if (!w1) w1 = p; else w2 = p; break;
            case NE * DDIM:        if (n4096 < 2) p4096[n4096++] = p; break;
            case DDIM:             if (n512 < 2) p512[n512++] = p; break;
            default: break;
        }
    }
    if (n_in >= 9) {
        if (!inp)  inp = (const float*)d_in[0];
        if (n4096 < 1) p4096[n4096++] = (const float*)d_in[1];
        if (!gb)   gb  = (const float*)d_in[2];
        if (!w1)   w1  = (const float*)d_in[3];
        if (!b1)   b1  = (const float*)d_in[4];
        if (!w2)   w2  = (const float*)d_in[5];
        if (n4096 < 2) p4096[n4096++] = (const float*)d_in[6];
        if (n512 < 1)  p512[n512++]   = (const float*)d_in[7];
        if (n512 < 2)  p512[n512++]   = (const float*)d_in[8];
    }
    if (n4096 == 1) p4096[1] = p4096[0];
    if (n512 == 1)  p512[1]  = p512[0];
    float* out = (float*)d_out;

    zero_cnt_kernel<<<1, 32>>>();
    gate_kernel<<<NTOK / 8, 256>>>(inp, p4096[0], p4096[1], gb);
    pad_rows_kernel<<<NE, 256>>>();

    // FC1 + GeLU: (NSLOT x DDIM) @ (HDIM x DDIM)^T per expert -> g_hidden
    moe_gemm_tc<128, 128, DDIM, HDIM, true, false, false>
        <<<dim3(HDIM / 128, NSLOT / 128, NE), 256>>>(inp, w1, b1, b1);

    // FC2: (NSLOT x HDIM) @ (DDIM x HDIM)^T per expert -> g_z
    moe_gemm_tc<128, 64, HDIM, DDIM, false, true, true>
        <<<dim3(DDIM / 64, NSLOT / 128, NE), 256>>>(nullptr, w2, p4096[0], p4096[1]);

    combine_ln_kernel<<<NTOK, 256>>>(p512[0], p512[1], out);

    diag_kernel<<<1, 256>>>(out);
}

// round 12
// speedup vs baseline: 3.6009x; 2.2416x over previous
#include <cuda_runtime.h>
#include <math.h>

#define NE     8
#define DDIM   512
#define HDIM   2048
#define NTOK   1024
#define NSLOT  2048   // NTOK * top_k

// ---------------- scratch (device globals; no allocation allowed) -----------
// Referenced ONLY from device code: passing a __device__ symbol as a kernel
// argument from host code yields the host shadow address (silent ATS write on
// GB300) — the R1-R6 bug.
__device__ __align__(16) float g_hidden[(size_t)NSLOT * HDIM];    // 16 MB
__device__ __align__(16) float g_z[(size_t)NSLOT * DDIM];         // 4 MB
__device__ __align__(16) float g_w1t[(size_t)NE * HDIM * DDIM];   // 33.5 MB (tf32-rounded)
__device__ __align__(16) float g_w2t[(size_t)NE * DDIM * HDIM];   // 33.5 MB (tf32-rounded)
__device__ __align__(16) float g_inpt[(size_t)NTOK * DDIM];       // 2 MB  (tf32-rounded)
__device__ int   g_rows[NE * NSLOT];
__device__ int   g_cnt[NE];
__device__ float g_score[NSLOT];

__device__ __forceinline__ bool is_zero8(const float* p) {
    float s = 0.f;
#pragma unroll
    for (int i = 0; i < 8; i++) s += fabsf(p[i]);
    return s == 0.f;
}

__device__ __forceinline__ unsigned f2tf32(float v) {
    unsigned u;
    asm("cvt.rna.tf32.f32 %0, %1;" : "=r"(u) : "f"(v));
    return u;
}

__device__ __forceinline__ void mma_tf32(float c[4], unsigned a0, unsigned a1,
                                         unsigned a2, unsigned a3,
                                         unsigned b0, unsigned b1) {
    asm volatile(
        "mma.sync.aligned.m16n8k8.row.col.f32.tf32.tf32.f32 "
        "{%0,%1,%2,%3}, {%4,%5,%6,%7}, {%8,%9}, {%0,%1,%2,%3};"
        : "+f"(c[0]), "+f"(c[1]), "+f"(c[2]), "+f"(c[3])
        : "r"(a0), "r"(a1), "r"(a2), "r"(a3), "r"(b0), "r"(b1));
}

// ---------------- init -------------------------------------------------------
__global__ void zero_cnt_kernel() {
    if (threadIdx.x < NE) g_cnt[threadIdx.x] = 0;
}

// ---------------- pre-round inputs/weights to tf32 (RNA), into scratch ------
// WHICH: 0 = w1 -> g_w1t, 1 = w2 -> g_w2t, 2 = inp -> g_inpt
template <int WHICH>
__global__ void cvt_tf32_kernel(const float* __restrict__ src, int nf4) {
    float* dst = (WHICH == 0) ? g_w1t : (WHICH == 1) ? g_w2t : g_inpt;
    int i = blockIdx.x * blockDim.x + threadIdx.x;
    int stride = gridDim.x * blockDim.x;
    for (; i < nf4; i += stride) {
        float4 v = ((const float4*)src)[i];
        v.x = __uint_as_float(f2tf32(v.x));
        v.y = __uint_as_float(f2tf32(v.y));
        v.z = __uint_as_float(f2tf32(v.z));
        v.w = __uint_as_float(f2tf32(v.w));
        ((float4*)dst)[i] = v;
    }
}

// ---------------- gate: logits -> top2 -> softmax -> bin --------------------
__global__ void gate_kernel(const float* __restrict__ inp,
                            const float* __restrict__ c0,
                            const float* __restrict__ c1,
                            const float* __restrict__ gb) {
    const float* gw = is_zero8(c0) ? c1 : c0;

    int warp = threadIdx.x >> 5;
    int lane = threadIdx.x & 31;
    int n = blockIdx.x * (blockDim.x >> 5) + warp;
    if (n >= NTOK) return;

    float acc[NE];
#pragma unroll
    for (int e = 0; e < NE; e++) acc[e] = 0.f;

    const float* x = inp + (size_t)n * DDIM;
    for (int d = lane; d < DDIM; d += 32) {
        float xv = x[d];
#pragma unroll
        for (int e = 0; e < NE; e++) acc[e] += xv * gw[e * DDIM + d];
    }
#pragma unroll
    for (int e = 0; e < NE; e++) {
#pragma unroll
        for (int off = 16; off; off >>= 1)
            acc[e] += __shfl_xor_sync(0xFFFFFFFFu, acc[e], off);
    }
    if (lane == 0) {
        float v0 = -1e30f, v1 = -1e30f;
        int i0 = 0, i1 = 0;
#pragma unroll
        for (int e = 0; e < NE; e++) {
            float v = acc[e] + gb[e];
            if (v > v0) { v1 = v0; i1 = i0; v0 = v; i0 = e; }
            else if (v > v1) { v1 = v; i1 = e; }
        }
        float ex = expf(v1 - v0);
        float s0 = 1.f / (1.f + ex);
        float s1 = ex * s0;
        g_score[2 * n + 0] = s0;
        g_score[2 * n + 1] = s1;
        int p0 = atomicAdd(&g_cnt[i0], 1);
        g_rows[i0 * NSLOT + p0] = 2 * n;
        int p1 = atomicAdd(&g_cnt[i1], 1);
        g_rows[i1 * NSLOT + p1] = 2 * n + 1;
    }
}

// ---------------- pad row lists to full length with -1 ----------------------
__global__ void pad_rows_kernel() {
    int e = blockIdx.x;
    int cnt = g_cnt[e];
    for (int i = cnt + threadIdx.x; i < NSLOT; i += blockDim.x)
        g_rows[e * NSLOT + i] = -1;
}

// ---------------- grouped GEMM via mma.sync tf32 + cp.async double buffer ---
// 512 threads = 16 warps in a 4x4 grid. Warp tile 32 x (TN/4).
// Data (A, W) is pre-rounded to tf32 in gmem -> staging is a pure byte copy.
template <int TM, int TN, int KT, int KK, int NOUT, bool GELU, bool PICK_ZERO_BIAS, bool FC2F>
__global__ void __launch_bounds__(512, 1)
moe_gemm_tc(const float* __restrict__ bias0, const float* __restrict__ bias1) {
    constexpr int SA  = KT + 4;
    constexpr int WN  = TN / 4;
    constexpr int MI  = 2;            // 32 rows / 16
    constexpr int NI  = WN / 8;
    constexpr int BUF = (TM + TN) * SA;
    constexpr int KQ  = KT / 4;       // float4 per row per tile

    extern __shared__ float S[];
    __shared__ int sslot[TM];

    const float* A    = FC2F ? g_hidden : g_inpt;
    const float* Wt   = FC2F ? g_w2t : g_w1t;
    float*       Cout = FC2F ? g_z : g_hidden;
    const int    lda  = FC2F ? HDIM : DDIM;

    const float* bias = bias0;
    if (PICK_ZERO_BIAS) bias = is_zero8(bias0) ? bias0 : bias1;

    const int e  = blockIdx.z;
    const int rt = blockIdx.y;
    const int ct = blockIdx.x;

    const int t    = threadIdx.x;
    const int wid  = t >> 5;
    const int lane = t & 31;
    const int wy   = wid >> 2;        // 0..3
    const int wx   = wid & 3;         // 0..3
    const int g    = lane >> 2;       // 0..7
    const int tk   = lane & 3;        // 0..3

    const int* rows = g_rows + e * NSLOT + rt * TM;
    for (int i = t; i < TM; i += 512) sslot[i] = rows[i];
    __syncthreads();
    if (sslot[0] < 0) return;         // packed list => whole tile empty

    const float* Wb = Wt + (size_t)e * NOUT * KK + (size_t)(ct * TN) * KK;
    const unsigned sbase = (unsigned)__cvta_generic_to_shared(S);

    float acc[MI][NI][4];
#pragma unroll
    for (int mi = 0; mi < MI; mi++)
#pragma unroll
        for (int ni = 0; ni < NI; ni++)
#pragma unroll
            for (int q = 0; q < 4; q++) acc[mi][ni][q] = 0.f;

    auto stageAB = [&](int b, int k0) {
        const unsigned abase = sbase + (unsigned)(b * BUF) * 4u;
        const unsigned bbase = abase + (unsigned)(TM * SA) * 4u;
        constexpr int AF4 = TM * KQ;
#pragma unroll
        for (int f = t; f < AF4; f += 512) {
            int row = f / KQ, q = f % KQ;
            int slot = sslot[row];
            int arow = slot < 0 ? 0 : (FC2F ? slot : (slot >> 1));
            const float* src = A + (size_t)arow * lda + k0 + q * 4;
            unsigned dst = abase + (unsigned)(row * SA + q * 4) * 4u;
            int sz = slot < 0 ? 0 : 16;
            asm volatile("cp.async.cg.shared.global [%0], [%1], 16, %2;\n"
                         :: "r"(dst), "l"(src), "r"(sz));
        }
        constexpr int BF4 = TN * KQ;
#pragma unroll
        for (int f = t; f < BF4; f += 512) {
            int row = f / KQ, q = f % KQ;
            const float* src = Wb + (size_t)row * KK + k0 + q * 4;
            unsigned dst = bbase + (unsigned)(row * SA + q * 4) * 4u;
            asm volatile("cp.async.cg.shared.global [%0], [%1], 16;\n"
                         :: "r"(dst), "l"(src));
        }
        asm volatile("cp.async.commit_group;\n");
    };

    const int NKI = KK / KT;
    stageAB(0, 0);
    for (int it = 0; it < NKI; it++) {
        if (it + 1 < NKI) {
            stageAB((it + 1) & 1, (it + 1) * KT);
            asm volatile("cp.async.wait_group 1;\n");
        } else {
            asm volatile("cp.async.wait_group 0;\n");
        }
        __syncthreads();

        const float* Sa = S + (it & 1) * BUF;
        const float* Sb = Sa + TM * SA;
#pragma unroll
        for (int kc = 0; kc < KT; kc += 8) {
            unsigned af[MI][4];
#pragma unroll
            for (int mi = 0; mi < MI; mi++) {
                int m = wy * 32 + mi * 16;
                af[mi][0] = __float_as_uint(Sa[(m + g) * SA + kc + tk]);
                af[mi][1] = __float_as_uint(Sa[(m + g + 8) * SA + kc + tk]);
                af[mi][2] = __float_as_uint(Sa[(m + g) * SA + kc + tk + 4]);
                af[mi][3] = __float_as_uint(Sa[(m + g + 8) * SA + kc + tk + 4]);
            }
#pragma unroll
            for (int ni = 0; ni < NI; ni++) {
                int n = wx * WN + ni * 8;
                unsigned b0 = __float_as_uint(Sb[(n + g) * SA + kc + tk]);
                unsigned b1 = __float_as_uint(Sb[(n + g) * SA + kc + tk + 4]);
#pragma unroll
                for (int mi = 0; mi < MI; mi++)
                    mma_tf32(acc[mi][ni], af[mi][0], af[mi][1], af[mi][2], af[mi][3], b0, b1);
            }
        }
        __syncthreads();
    }

    // epilogue: bias (+gelu), scatter to Cout rows by slot.
    // FC1 output is rounded to tf32 so FC2 can stage it as a raw copy.
    const int colbase = ct * TN + wx * WN;
#pragma unroll
    for (int mi = 0; mi < MI; mi++) {
        int lr0 = wy * 32 + mi * 16 + g;
        int slot0 = sslot[lr0];
        int slot1 = sslot[lr0 + 8];
#pragma unroll
        for (int ni = 0; ni < NI; ni++) {
            int col = colbase + ni * 8 + 2 * tk;
            float b0 = bias[e * NOUT + col];
            float b1 = bias[e * NOUT + col + 1];
            if (slot0 >= 0) {
                float v0 = acc[mi][ni][0] + b0;
                float v1 = acc[mi][ni][1] + b1;
                if (GELU) {
                    v0 = 0.5f * v0 * (1.f + erff(v0 * 0.70710678118654752f));
                    v1 = 0.5f * v1 * (1.f + erff(v1 * 0.70710678118654752f));
                }
                if (!FC2F) {
                    v0 = __uint_as_float(f2tf32(v0));
                    v1 = __uint_as_float(f2tf32(v1));
                }
                *(float2*)&Cout[(size_t)slot0 * NOUT + col] = make_float2(v0, v1);
            }
            if (slot1 >= 0) {
                float v2 = acc[mi][ni][2] + b0;
                float v3 = acc[mi][ni][3] + b1;
                if (GELU) {
                    v2 = 0.5f * v2 * (1.f + erff(v2 * 0.70710678118654752f));
                    v3 = 0.5f * v3 * (1.f + erff(v3 * 0.70710678118654752f));
                }
                if (!FC2F) {
                    v2 = __uint_as_float(f2tf32(v2));
                    v3 = __uint_as_float(f2tf32(v3));
                }
                *(float2*)&Cout[(size_t)slot1 * NOUT + col] = make_float2(v2, v3);
            }
        }
    }
}

// ---------------- combine (top-2 weighted sum) + LayerNorm ------------------
__global__ void combine_ln_kernel(const float* __restrict__ l0,
                                  const float* __restrict__ l1,
                                  float* __restrict__ out) {
    const float* ln_b = is_zero8(l0) ? l0 : l1;
    const float* ln_w = is_zero8(l0) ? l1 : l0;

    const int n = blockIdx.x;
    const int t = threadIdx.x;  // 256 threads
    __shared__ float buf[DDIM];
    __shared__ float wsum[8], wsq[8];

    float s0 = g_score[2 * n + 0];
    float s1 = g_score[2 * n + 1];
    const float* z0 = g_z + (size_t)(2 * n + 0) * DDIM;
    const float* z1 = g_z + (size_t)(2 * n + 1) * DDIM;

    float sum = 0.f, sq = 0.f;
    for (int d = t; d < DDIM; d += 256) {
        float v = s0 * z0[d] + s1 * z1[d];
        buf[d] = v;
        sum += v;
        sq += v * v;
    }
#pragma unroll
    for (int off = 16; off; off >>= 1) {
        sum += __shfl_xor_sync(0xFFFFFFFFu, sum, off);
        sq  += __shfl_xor_sync(0xFFFFFFFFu, sq, off);
    }
    int warp = t >> 5, lane = t & 31;
    if (lane == 0) { wsum[warp] = sum; wsq[warp] = sq; }
    __syncthreads();
    if (warp == 0) {
        float s = (lane < 8) ? wsum[lane] : 0.f;
        float q = (lane < 8) ? wsq[lane] : 0.f;
#pragma unroll
        for (int off = 4; off; off >>= 1) {
            s += __shfl_xor_sync(0xFFFFFFFFu, s, off);
            q += __shfl_xor_sync(0xFFFFFFFFu, q, off);
        }
        if (lane == 0) { wsum[0] = s; wsq[0] = q; }
    }
    __syncthreads();
    float mean = wsum[0] * (1.f / DDIM);
    float var  = wsq[0] * (1.f / DDIM) - mean * mean;
    float inv  = rsqrtf(var + 1e-5f);
    for (int d = t; d < DDIM; d += 256) {
        out[(size_t)n * DDIM + d] = (buf[d] - mean) * inv * ln_w[d] + ln_b[d];
    }
}

// ---------------- slim diagnostic (writes only on invariant failure) --------
__global__ void diag_kernel(float* out) {
    __shared__ float sC;
    if (threadIdx.x == 0) {
        float C = 0.f;
        int s = 0;
        for (int e = 0; e < NE; e++) s += g_cnt[e];
        if (s != NSLOT) C = 2.f;
        else {
            bool hz = true;
            for (int i = 0; i < 256 && hz; i++)
                if (g_hidden[(size_t)i * 8192] != 0.f) hz = false;
            if (hz) C = 5.f;
            else {
                bool zz = true;
                for (int i = 0; i < 256 && zz; i++)
                    if (g_z[(size_t)i * 4093] != 0.f) zz = false;
                if (zz) C = 9.f;
            }
        }
        sC = C;
    }
    __syncthreads();
    float C = sC;
    if (C != 0.f) {
        for (size_t i = threadIdx.x; i < (size_t)NTOK * DDIM; i += blockDim.x)
            out[i] = C;
    }
}

// ---------------- launch -----------------------------------------------------
extern "C" void kernel_launch(void* const* d_in, const int* in_sizes, int n_in,
                              void* d_out, int out_size) {
    (void)out_size;
    const float *inp = nullptr, *gb = nullptr, *b1 = nullptr;
    const float *w1 = nullptr, *w2 = nullptr;
    const float *p4096[2] = {nullptr, nullptr};
    const float *p512[2]  = {nullptr, nullptr};
    int n4096 = 0, n512 = 0;

    for (int i = 0; i < n_in; i++) {
        const float* p = (const float*)d_in[i];
        switch (in_sizes[i]) {
            case NTOK * DDIM:      inp = p; break;
            case NE:               gb = p; break;
            case NE * HDIM:        b1 = p; break;
            case NE * HDIM * DDIM: if (!w1) w1 = p; else w2 = p; break;
            case NE * DDIM:        if (n4096 < 2) p4096[n4096++] = p; break;
            case DDIM:             if (n512 < 2) p512[n512++] = p; break;
            default: break;
        }
    }
    if (n_in >= 9) {
        if (!inp)  inp = (const float*)d_in[0];
        if (n4096 < 1) p4096[n4096++] = (const float*)d_in[1];
        if (!gb)   gb  = (const float*)d_in[2];
        if (!w1)   w1  = (const float*)d_in[3];
        if (!b1)   b1  = (const float*)d_in[4];
        if (!w2)   w2  = (const float*)d_in[5];
        if (n4096 < 2) p4096[n4096++] = (const float*)d_in[6];
        if (n512 < 1)  p512[n512++]   = (const float*)d_in[7];
        if (n512 < 2)  p512[n512++]   = (const float*)d_in[8];
    }
    if (n4096 == 1) p4096[1] = p4096[0];
    if (n512 == 1)  p512[1]  = p512[0];
    float* out = (float*)d_out;

    // opt-in smem for the big tiles (idempotent, capture-safe)
    constexpr int SMEM1 = 2 * (128 + 128) * 68 * 4;   // 139264 B
    constexpr int SMEM2 = 2 * (128 + 64) * 68 * 4;    // 104448 B
    cudaFuncSetAttribute(moe_gemm_tc<128, 128, 64, DDIM, HDIM, true, false, false>,
                         cudaFuncAttributeMaxDynamicSharedMemorySize, SMEM1);
    cudaFuncSetAttribute(moe_gemm_tc<128, 64, 64, HDIM, DDIM, false, true, true>,
                         cudaFuncAttributeMaxDynamicSharedMemorySize, SMEM2);

    zero_cnt_kernel<<<1, 32>>>();
    cvt_tf32_kernel<2><<<256, 256>>>(inp, NTOK * DDIM / 4);
    cvt_tf32_kernel<0><<<1024, 256>>>(w1, NE * HDIM * DDIM / 4);
    cvt_tf32_kernel<1><<<1024, 256>>>(w2, NE * DDIM * HDIM / 4);
    gate_kernel<<<NTOK / 8, 256>>>(inp, p4096[0], p4096[1], gb);
    pad_rows_kernel<<<NE, 256>>>();

    // FC1 + GeLU: (NSLOT x DDIM) @ (HDIM x DDIM)^T per expert -> g_hidden
    moe_gemm_tc<128, 128, 64, DDIM, HDIM, true, false, false>
        <<<dim3(HDIM / 128, NSLOT / 128, NE), 512, SMEM1>>>(b1, b1);

    // FC2: (NSLOT x HDIM) @ (DDIM x HDIM)^T per expert -> g_z
    moe_gemm_tc<128, 64, 64, HDIM, DDIM, false, true, true>
        <<<dim3(DDIM / 64, NSLOT / 128, NE), 512, SMEM2>>>(p4096[0], p4096[1]);

    combine_ln_kernel<<<NTOK, 256>>>(p512[0], p512[1], out);

    diag_kernel<<<1, 256>>>(out);
}

// round 13
// speedup vs baseline: 3.9814x; 1.1057x over previous
#include <cuda_runtime.h>
#include <math.h>

#define NE     8
#define DDIM   512
#define HDIM   2048
#define NTOK   1024
#define NSLOT  2048   // NTOK * top_k

// ---------------- scratch (device globals; no allocation allowed) -----------
// Referenced ONLY from device code: passing a __device__ symbol as a kernel
// argument from host code yields the host shadow address (silent ATS write on
// GB300) — the R1-R6 bug.
__device__ __align__(16) float g_hidden[(size_t)NSLOT * HDIM];    // 16 MB
__device__ __align__(16) float g_z[(size_t)NSLOT * DDIM];         // 4 MB
__device__ int   g_rows[NE * NSLOT];
__device__ int   g_cnt[NE];
__device__ float g_score[NSLOT];

__device__ __forceinline__ bool is_zero8(const float* p) {
    float s = 0.f;
#pragma unroll
    for (int i = 0; i < 8; i++) s += fabsf(p[i]);
    return s == 0.f;
}

__device__ __forceinline__ unsigned f2tf32(float v) {
    unsigned u;
    asm("cvt.rna.tf32.f32 %0, %1;" : "=r"(u) : "f"(v));
    return u;
}

__device__ __forceinline__ void mma_tf32(float c[4], unsigned a0, unsigned a1,
                                         unsigned a2, unsigned a3,
                                         unsigned b0, unsigned b1) {
    asm volatile(
        "mma.sync.aligned.m16n8k8.row.col.f32.tf32.tf32.f32 "
        "{%0,%1,%2,%3}, {%4,%5,%6,%7}, {%8,%9}, {%0,%1,%2,%3};"
        : "+f"(c[0]), "+f"(c[1]), "+f"(c[2]), "+f"(c[3])
        : "r"(a0), "r"(a1), "r"(a2), "r"(a3), "r"(b0), "r"(b1));
}

// ---------------- init -------------------------------------------------------
__global__ void zero_cnt_kernel() {
    if (threadIdx.x < NE) g_cnt[threadIdx.x] = 0;
}

// ---------------- gate: logits -> top2 -> softmax -> bin --------------------
__global__ void gate_kernel(const float* __restrict__ inp,
                            const float* __restrict__ c0,
                            const float* __restrict__ c1,
                            const float* __restrict__ gb) {
    const float* gw = is_zero8(c0) ? c1 : c0;

    int warp = threadIdx.x >> 5;
    int lane = threadIdx.x & 31;
    int n = blockIdx.x * (blockDim.x >> 5) + warp;
    if (n >= NTOK) return;

    float acc[NE];
#pragma unroll
    for (int e = 0; e < NE; e++) acc[e] = 0.f;

    const float* x = inp + (size_t)n * DDIM;
    for (int d = lane; d < DDIM; d += 32) {
        float xv = x[d];
#pragma unroll
        for (int e = 0; e < NE; e++) acc[e] += xv * gw[e * DDIM + d];
    }
#pragma unroll
    for (int e = 0; e < NE; e++) {
#pragma unroll
        for (int off = 16; off; off >>= 1)
            acc[e] += __shfl_xor_sync(0xFFFFFFFFu, acc[e], off);
    }
    if (lane == 0) {
        float v0 = -1e30f, v1 = -1e30f;
        int i0 = 0, i1 = 0;
#pragma unroll
        for (int e = 0; e < NE; e++) {
            float v = acc[e] + gb[e];
            if (v > v0) { v1 = v0; i1 = i0; v0 = v; i0 = e; }
            else if (v > v1) { v1 = v; i1 = e; }
        }
        float ex = expf(v1 - v0);
        float s0 = 1.f / (1.f + ex);
        float s1 = ex * s0;
        g_score[2 * n + 0] = s0;
        g_score[2 * n + 1] = s1;
        int p0 = atomicAdd(&g_cnt[i0], 1);
        g_rows[i0 * NSLOT + p0] = 2 * n;
        int p1 = atomicAdd(&g_cnt[i1], 1);
        g_rows[i1 * NSLOT + p1] = 2 * n + 1;
    }
}

// ---------------- pad row lists to full length with -1 ----------------------
__global__ void pad_rows_kernel() {
    int e = blockIdx.x;
    int cnt = g_cnt[e];
    for (int i = cnt + threadIdx.x; i < NSLOT; i += blockDim.x)
        g_rows[e * NSLOT + i] = -1;
}

// ---------------- grouped GEMM via mma.sync tf32 + cp.async double buffer ---
// 512 threads = 16 warps in a 4x4 grid. Warp tile 32 x (TN/4).
// Stages RAW fp32 via cp.async; tf32 RNA conversion is applied in-register to
// fragments (identical rounding points to the R12 pre-pass => same numerics).
template <int TM, int TN, int KT, int KK, int NOUT, bool GELU, bool PICK_ZERO_BIAS, bool FC2F>
__global__ void __launch_bounds__(512, 1)
moe_gemm_tc(const float* __restrict__ Ain,    // FC1: inp; FC2: unused
            const float* __restrict__ W,      // E x NOUT x KK (raw fp32)
            const float* __restrict__ bias0,
            const float* __restrict__ bias1) {
    constexpr int SA  = KT + 4;
    constexpr int WN  = TN / 4;
    constexpr int MI  = 2;            // 32 rows / 16
    constexpr int NI  = WN / 8;
    constexpr int BUF = (TM + TN) * SA;
    constexpr int KQ  = KT / 4;       // float4 per row per tile

    extern __shared__ float S[];
    __shared__ int sslot[TM];

    const float* A    = FC2F ? g_hidden : Ain;
    float*       Cout = FC2F ? g_z : g_hidden;
    const int    lda  = FC2F ? HDIM : DDIM;

    const float* bias = bias0;
    if (PICK_ZERO_BIAS) bias = is_zero8(bias0) ? bias0 : bias1;

    const int e  = blockIdx.z;
    const int rt = blockIdx.y;
    const int ct = blockIdx.x;

    const int t    = threadIdx.x;
    const int wid  = t >> 5;
    const int lane = t & 31;
    const int wy   = wid >> 2;        // 0..3
    const int wx   = wid & 3;         // 0..3
    const int g    = lane >> 2;       // 0..7
    const int tk   = lane & 3;        // 0..3

    const int* rows = g_rows + e * NSLOT + rt * TM;
    for (int i = t; i < TM; i += 512) sslot[i] = rows[i];
    __syncthreads();
    if (sslot[0] < 0) return;         // packed list => whole tile empty

    const float* Wb = W + (size_t)e * NOUT * KK + (size_t)(ct * TN) * KK;
    const unsigned sbase = (unsigned)__cvta_generic_to_shared(S);

    float acc[MI][NI][4];
#pragma unroll
    for (int mi = 0; mi < MI; mi++)
#pragma unroll
        for (int ni = 0; ni < NI; ni++)
#pragma unroll
            for (int q = 0; q < 4; q++) acc[mi][ni][q] = 0.f;

    auto stageAB = [&](int b, int k0) {
        const unsigned abase = sbase + (unsigned)(b * BUF) * 4u;
        const unsigned bbase = abase + (unsigned)(TM * SA) * 4u;
        constexpr int AF4 = TM * KQ;
#pragma unroll
        for (int f = t; f < AF4; f += 512) {
            int row = f / KQ, q = f % KQ;
            int slot = sslot[row];
            int arow = slot < 0 ? 0 : (FC2F ? slot : (slot >> 1));
            const float* src = A + (size_t)arow * lda + k0 + q * 4;
            unsigned dst = abase + (unsigned)(row * SA + q * 4) * 4u;
            int sz = slot < 0 ? 0 : 16;
            asm volatile("cp.async.cg.shared.global [%0], [%1], 16, %2;\n"
                         :: "r"(dst), "l"(src), "r"(sz));
        }
        constexpr int BF4 = TN * KQ;
#pragma unroll
        for (int f = t; f < BF4; f += 512) {
            int row = f / KQ, q = f % KQ;
            const float* src = Wb + (size_t)row * KK + k0 + q * 4;
            unsigned dst = bbase + (unsigned)(row * SA + q * 4) * 4u;
            asm volatile("cp.async.cg.shared.global [%0], [%1], 16;\n"
                         :: "r"(dst), "l"(src));
        }
        asm volatile("cp.async.commit_group;\n");
    };

    const int NKI = KK / KT;
    stageAB(0, 0);
    for (int it = 0; it < NKI; it++) {
        if (it + 1 < NKI) {
            stageAB((it + 1) & 1, (it + 1) * KT);
            asm volatile("cp.async.wait_group 1;\n");
        } else {
            asm volatile("cp.async.wait_group 0;\n");
        }
        __syncthreads();

        const float* Sa = S + (it & 1) * BUF;
        const float* Sb = Sa + TM * SA;
#pragma unroll
        for (int kc = 0; kc < KT; kc += 8) {
            unsigned af[MI][4];
#pragma unroll
            for (int mi = 0; mi < MI; mi++) {
                int m = wy * 32 + mi * 16;
                af[mi][0] = f2tf32(Sa[(m + g) * SA + kc + tk]);
                af[mi][1] = f2tf32(Sa[(m + g + 8) * SA + kc + tk]);
                af[mi][2] = f2tf32(Sa[(m + g) * SA + kc + tk + 4]);
                af[mi][3] = f2tf32(Sa[(m + g + 8) * SA + kc + tk + 4]);
            }
#pragma unroll
            for (int ni = 0; ni < NI; ni++) {
                int n = wx * WN + ni * 8;
                unsigned b0 = f2tf32(Sb[(n + g) * SA + kc + tk]);
                unsigned b1 = f2tf32(Sb[(n + g) * SA + kc + tk + 4]);
#pragma unroll
                for (int mi = 0; mi < MI; mi++)
                    mma_tf32(acc[mi][ni], af[mi][0], af[mi][1], af[mi][2], af[mi][3], b0, b1);
            }
        }
        __syncthreads();
    }

    // epilogue: bias (+gelu), scatter to Cout rows by slot.
    // No tf32 pre-rounding here: FC2's in-loop cvt performs the identical RNA.
    const int colbase = ct * TN + wx * WN;
#pragma unroll
    for (int mi = 0; mi < MI; mi++) {
        int lr0 = wy * 32 + mi * 16 + g;
        int slot0 = sslot[lr0];
        int slot1 = sslot[lr0 + 8];
#pragma unroll
        for (int ni = 0; ni < NI; ni++) {
            int col = colbase + ni * 8 + 2 * tk;
            float b0 = bias[e * NOUT + col];
            float b1 = bias[e * NOUT + col + 1];
            if (slot0 >= 0) {
                float v0 = acc[mi][ni][0] + b0;
                float v1 = acc[mi][ni][1] + b1;
                if (GELU) {
                    v0 = 0.5f * v0 * (1.f + erff(v0 * 0.70710678118654752f));
                    v1 = 0.5f * v1 * (1.f + erff(v1 * 0.70710678118654752f));
                }
                *(float2*)&Cout[(size_t)slot0 * NOUT + col] = make_float2(v0, v1);
            }
            if (slot1 >= 0) {
                float v2 = acc[mi][ni][2] + b0;
                float v3 = acc[mi][ni][3] + b1;
                if (GELU) {
                    v2 = 0.5f * v2 * (1.f + erff(v2 * 0.70710678118654752f));
                    v3 = 0.5f * v3 * (1.f + erff(v3 * 0.70710678118654752f));
                }
                *(float2*)&Cout[(size_t)slot1 * NOUT + col] = make_float2(v2, v3);
            }
        }
    }
}

// ---------------- combine (top-2 weighted sum) + LayerNorm ------------------
__global__ void combine_ln_kernel(const float* __restrict__ l0,
                                  const float* __restrict__ l1,
                                  float* __restrict__ out) {
    const float* ln_b = is_zero8(l0) ? l0 : l1;
    const float* ln_w = is_zero8(l0) ? l1 : l0;

    const int n = blockIdx.x;
    const int t = threadIdx.x;  // 256 threads
    __shared__ float buf[DDIM];
    __shared__ float wsum[8], wsq[8];

    float s0 = g_score[2 * n + 0];
    float s1 = g_score[2 * n + 1];
    const float* z0 = g_z + (size_t)(2 * n + 0) * DDIM;
    const float* z1 = g_z + (size_t)(2 * n + 1) * DDIM;

    float sum = 0.f, sq = 0.f;
    for (int d = t; d < DDIM; d += 256) {
        float v = s0 * z0[d] + s1 * z1[d];
        buf[d] = v;
        sum += v;
        sq += v * v;
    }
#pragma unroll
    for (int off = 16; off; off >>= 1) {
        sum += __shfl_xor_sync(0xFFFFFFFFu, sum, off);
        sq  += __shfl_xor_sync(0xFFFFFFFFu, sq, off);
    }
    int warp = t >> 5, lane = t & 31;
    if (lane == 0) { wsum[warp] = sum; wsq[warp] = sq; }
    __syncthreads();
    if (warp == 0) {
        float s = (lane < 8) ? wsum[lane] : 0.f;
        float q = (lane < 8) ? wsq[lane] : 0.f;
#pragma unroll
        for (int off = 4; off; off >>= 1) {
            s += __shfl_xor_sync(0xFFFFFFFFu, s, off);
            q += __shfl_xor_sync(0xFFFFFFFFu, q, off);
        }
        if (lane == 0) { wsum[0] = s; wsq[0] = q; }
    }
    __syncthreads();
    float mean = wsum[0] * (1.f / DDIM);
    float var  = wsq[0] * (1.f / DDIM) - mean * mean;
    float inv  = rsqrtf(var + 1e-5f);
    for (int d = t; d < DDIM; d += 256) {
        out[(size_t)n * DDIM + d] = (buf[d] - mean) * inv * ln_w[d] + ln_b[d];
    }
}

// ---------------- slim diagnostic (writes only on invariant failure) --------
__global__ void diag_kernel(float* out) {
    __shared__ float sC;
    if (threadIdx.x == 0) {
        float C = 0.f;
        int s = 0;
        for (int e = 0; e < NE; e++) s += g_cnt[e];
        if (s != NSLOT) C = 2.f;
        else {
            bool hz = true;
            for (int i = 0; i < 256 && hz; i++)
                if (g_hidden[(size_t)i * 8192] != 0.f) hz = false;
            if (hz) C = 5.f;
            else {
                bool zz = true;
                for (int i = 0; i < 256 && zz; i++)
                    if (g_z[(size_t)i * 4093] != 0.f) zz = false;
                if (zz) C = 9.f;
            }
        }
        sC = C;
    }
    __syncthreads();
    float C = sC;
    if (C != 0.f) {
        for (size_t i = threadIdx.x; i < (size_t)NTOK * DDIM; i += blockDim.x)
            out[i] = C;
    }
}

// ---------------- launch -----------------------------------------------------
extern "C" void kernel_launch(void* const* d_in, const int* in_sizes, int n_in,
                              void* d_out, int out_size) {
    (void)out_size;
    const float *inp = nullptr, *gb = nullptr, *b1 = nullptr;
    const float *w1 = nullptr, *w2 = nullptr;
    const float *p4096[2] = {nullptr, nullptr};
    const float *p512[2]  = {nullptr, nullptr};
    int n4096 = 0, n512 = 0;

    for (int i = 0; i < n_in; i++) {
        const float* p = (const float*)d_in[i];
        switch (in_sizes[i]) {
            case NTOK * DDIM:      inp = p; break;
            case NE:               gb = p; break;
            case NE * HDIM:        b1 = p; break;
            case NE * HDIM * DDIM: if (!w1) w1 = p; else w2 = p; break;
            case NE * DDIM:        if (n4096 < 2) p4096[n4096++] = p; break;
            case DDIM:             if (n512 < 2) p512[n512++] = p; break;
            default: break;
        }
    }
    if (n_in >= 9) {
        if (!inp)  inp = (const float*)d_in[0];
        if (n4096 < 1) p4096[n4096++] = (const float*)d_in[1];
        if (!gb)   gb  = (const float*)d_in[2];
        if (!w1)   w1  = (const float*)d_in[3];
        if (!b1)   b1  = (const float*)d_in[4];
        if (!w2)   w2  = (const float*)d_in[5];
        if (n4096 < 2) p4096[n4096++] = (const float*)d_in[6];
        if (n512 < 1)  p512[n512++]   = (const float*)d_in[7];
        if (n512 < 2)  p512[n512++]   = (const float*)d_in[8];
    }
    if (n4096 == 1) p4096[1] = p4096[0];
    if (n512 == 1)  p512[1]  = p512[0];
    float* out = (float*)d_out;

    // opt-in smem for the big tiles (idempotent, capture-safe)
    constexpr int SMEM1 = 2 * (128 + 128) * 68 * 4;   // 139264 B
    constexpr int SMEM2 = 2 * (128 + 64) * 68 * 4;    // 104448 B
    cudaFuncSetAttribute(moe_gemm_tc<128, 128, 64, DDIM, HDIM, true, false, false>,
                         cudaFuncAttributeMaxDynamicSharedMemorySize, SMEM1);
    cudaFuncSetAttribute(moe_gemm_tc<128, 64, 64, HDIM, DDIM, false, true, true>,
                         cudaFuncAttributeMaxDynamicSharedMemorySize, SMEM2);

    zero_cnt_kernel<<<1, 32>>>();
    gate_kernel<<<NTOK / 8, 256>>>(inp, p4096[0], p4096[1], gb);
    pad_rows_kernel<<<NE, 256>>>();

    // FC1 + GeLU: (NSLOT x DDIM) @ (HDIM x DDIM)^T per expert -> g_hidden
    moe_gemm_tc<128, 128, 64, DDIM, HDIM, true, false, false>
        <<<dim3(HDIM / 128, NSLOT / 128, NE), 512, SMEM1>>>(inp, w1, b1, b1);

    // FC2: (NSLOT x HDIM) @ (DDIM x HDIM)^T per expert -> g_z
    moe_gemm_tc<128, 64, 64, HDIM, DDIM, false, true, true>
        <<<dim3(DDIM / 64, NSLOT / 128, NE), 512, SMEM2>>>(nullptr, w2, p4096[0], p4096[1]);

    combine_ln_kernel<<<NTOK, 256>>>(p512[0], p512[1], out);

    diag_kernel<<<1, 256>>>(out);
}